// round 1
// baseline (speedup 1.0000x reference)
#include <cuda_runtime.h>
#include <cuda_fp16.h>
#include <cstdint>

#define LDA 136          // padded row stride in halves (128 + 8) -> conflict-free ldmatrix
#define TB  128          // batch rows per CTA
#define SMEM_BYTES (6*128*LDA*2 + 1024*4)

// ---------------- scratch (device globals: no allocation allowed) ----------------
__device__ __half g_WiM[(size_t)128*128*128];   // [i][j][k] fp16, = Wi[i,j,k]*M[k,i]
__device__ float  g_wz [128*128];               // [i][j]  z-column weight (Wi[i,j,128])
__device__ __half g_W1h[128*128];
__device__ __half g_W2h[128*128];
__device__ float  g_zT [(size_t)128*131072];    // transposed z: [i][b]

// ---------------- prologue: weight prep ----------------
__global__ void prep_weights(const float* __restrict__ Wi, const float* __restrict__ M,
                             const float* __restrict__ W1, const float* __restrict__ W2) {
    int i = blockIdx.x;
    if (i < 128) {
        const float* Wii = Wi + (size_t)i * 16512;   // 128*129
        for (int v = threadIdx.x; v < 16384; v += blockDim.x) {
            int j = v >> 7, k = v & 127;
            float m = (k == i) ? 0.f : M[k * 128 + i];
            g_WiM[(size_t)i * 16384 + v] = __float2half(Wii[j * 129 + k] * m);
        }
        for (int j = threadIdx.x; j < 128; j += blockDim.x)
            g_wz[i * 128 + j] = Wii[j * 129 + 128];
    } else if (i == 128) {
        for (int v = threadIdx.x; v < 16384; v += blockDim.x) g_W1h[v] = __float2half(W1[v]);
    } else {
        for (int v = threadIdx.x; v < 16384; v += blockDim.x) g_W2h[v] = __float2half(W2[v]);
    }
}

// ---------------- prologue: z transpose ----------------
__global__ void transpose_z(const float* __restrict__ z, int Bn) {
    __shared__ float t[32][33];
    int b0 = blockIdx.x * 32, i0 = blockIdx.y * 32;
    #pragma unroll
    for (int r = threadIdx.y; r < 32; r += 8)
        t[r][threadIdx.x] = z[(size_t)(b0 + r) * 128 + i0 + threadIdx.x];
    __syncthreads();
    #pragma unroll
    for (int r = threadIdx.y; r < 32; r += 8)
        g_zT[(size_t)(i0 + r) * Bn + b0 + threadIdx.x] = t[threadIdx.x][r];
}

// ---------------- mma helpers ----------------
__device__ __forceinline__ void ldsm4(uint32_t addr, uint32_t* r) {
    asm volatile("ldmatrix.sync.aligned.m8n8.x4.shared.b16 {%0,%1,%2,%3},[%4];"
        : "=r"(r[0]), "=r"(r[1]), "=r"(r[2]), "=r"(r[3]) : "r"(addr));
}
__device__ __forceinline__ void mma16816(float* c, const uint32_t* a, const uint32_t* b) {
    asm volatile("mma.sync.aligned.m16n8k16.row.col.f32.f16.f16.f32 "
        "{%0,%1,%2,%3},{%4,%5,%6,%7},{%8,%9},{%0,%1,%2,%3};"
        : "+f"(c[0]), "+f"(c[1]), "+f"(c[2]), "+f"(c[3])
        : "r"(a[0]), "r"(a[1]), "r"(a[2]), "r"(a[3]), "r"(b[0]), "r"(b[1]));
}
__device__ __forceinline__ void cpa16(uint32_t s, const void* g) {
    asm volatile("cp.async.ca.shared.global [%0],[%1],16;\n" :: "r"(s), "l"(g));
}

// C[128,128] += A[128,128(k)] * B[128(n),128(k)]^T ; A,B fp16 in smem (padded LDA)
__device__ __forceinline__ void gemm128(uint32_t aBase, uint32_t bBase,
                                        int lane, int mrow, int ncol, float acc[2][8][4]) {
    #pragma unroll
    for (int mt = 0; mt < 2; mt++)
        #pragma unroll
        for (int nt = 0; nt < 8; nt++)
            #pragma unroll
            for (int c = 0; c < 4; c++) acc[mt][nt][c] = 0.f;

    uint32_t aOff = aBase + (uint32_t)(((mrow + (lane & 15)) * LDA + ((lane & 16) ? 8 : 0)) * 2);
    uint32_t bOff = bBase + (uint32_t)(((ncol + (lane & 7) + ((lane & 16) ? 8 : 0)) * LDA
                                       + ((lane & 8) ? 8 : 0)) * 2);
    #pragma unroll
    for (int ks = 0; ks < 8; ks++) {
        uint32_t kb = ks * 32;   // 16 halves
        uint32_t a0[4], a1[4], b[16];
        ldsm4(aOff + kb, a0);
        ldsm4(aOff + 16 * LDA * 2 + kb, a1);
        #pragma unroll
        for (int q = 0; q < 4; q++) ldsm4(bOff + q * 16 * LDA * 2 + kb, b + 4 * q);
        #pragma unroll
        for (int nt = 0; nt < 8; nt++) {
            const uint32_t* bb = b + (nt >> 1) * 4 + (nt & 1) * 2;
            mma16816(acc[0][nt], a0, bb);
            mma16816(acc[1][nt], a1, bb);
        }
    }
}

// ---------------- main persistent-tile scan kernel ----------------
__global__ __launch_bounds__(256, 1) void gen_main(
    const float* __restrict__ x,  const float* __restrict__ bi, const float* __restrict__ Wf,
    const float* __restrict__ bf, const float* __restrict__ b1, const float* __restrict__ b2,
    float* __restrict__ out, int Bn)
{
    extern __shared__ char smem_raw[];
    __half* sOut = (__half*)smem_raw;            // activations (fp16 "out" tile)
    __half* sHA  = sOut  + 128 * LDA;
    __half* sHB  = sHA   + 128 * LDA;
    __half* sWiM = sHB   + 128 * LDA;
    __half* sW1  = sWiM  + 128 * LDA;
    __half* sW2  = sW1   + 128 * LDA;
    float* sF  = (float*)(sW2 + 128 * LDA);
    float* sZ  = sF;        float* sWz = sF + 128;  float* sBi = sF + 256;
    float* sB1 = sF + 384;  float* sB2 = sF + 512;  float* sWf = sF + 640;
    float* sO2 = sF + 768;  // [2][128]

    int tid = threadIdx.x, lane = tid & 31, wid = tid >> 5;
    int wm = wid >> 1, wn = wid & 1;
    int mrow = wm * 32, ncol = wn * 64;
    int gr0 = lane >> 2, gc0 = 2 * (lane & 3);
    size_t b0 = (size_t)blockIdx.x * TB;

    uint32_t sOutA = (uint32_t)__cvta_generic_to_shared(sOut);
    uint32_t sHAA  = (uint32_t)__cvta_generic_to_shared(sHA);
    uint32_t sHBA  = (uint32_t)__cvta_generic_to_shared(sHB);
    uint32_t sWiMA = (uint32_t)__cvta_generic_to_shared(sWiM);
    uint32_t sW1A  = (uint32_t)__cvta_generic_to_shared(sW1);
    uint32_t sW2A  = (uint32_t)__cvta_generic_to_shared(sW2);

    // stage x -> sOut (fp16)
    const float4* xg = (const float4*)(x + b0 * 128);
    #pragma unroll
    for (int q = 0; q < 16; q++) {
        int v = q * 256 + tid;
        float4 f = xg[v];
        __half2* p = (__half2*)(sOut + (v >> 5) * LDA + (v & 31) * 4);
        p[0] = __floats2half2_rn(f.x, f.y);
        p[1] = __floats2half2_rn(f.z, f.w);
    }
    // stage W1, W2
    #pragma unroll
    for (int q = 0; q < 8; q++) {
        int v = q * 256 + tid, j = v >> 4, k = (v & 15) * 8;
        *(uint4*)(sW1 + j * LDA + k) = ((const uint4*)g_W1h)[v];
        *(uint4*)(sW2 + j * LDA + k) = ((const uint4*)g_W2h)[v];
    }
    if (tid < 128) { sB1[tid] = b1[tid]; sB2[tid] = b2[tid]; }
    // stage WiM_0 via cp.async
    {
        const uint4* src = (const uint4*)g_WiM;
        #pragma unroll
        for (int q = 0; q < 8; q++) {
            int v = q * 256 + tid, j = v >> 4, k = (v & 15) * 8;
            cpa16(sWiMA + (j * LDA + k) * 2, src + v);
        }
        asm volatile("cp.async.commit_group;\n");
        asm volatile("cp.async.wait_group 0;\n");
    }
    __syncthreads();

    float acc[2][8][4];
    for (int i = 0; i < 128; i++) {
        if (tid < 128) {
            sZ[tid]  = g_zT[(size_t)i * Bn + b0 + tid];
            sWz[tid] = g_wz[i * 128 + tid];
            sBi[tid] = bi[i * 128 + tid];
            sWf[tid] = Wf[i * 128 + tid];
        }
        __syncthreads();

        // ---- GEMM0: h1 = relu(out @ WiM^T + z*wz + bi) ----
        gemm128(sOutA, sWiMA, lane, mrow, ncol, acc);
        #pragma unroll
        for (int mt = 0; mt < 2; mt++) {
            int r0 = mrow + mt * 16 + gr0, r1 = r0 + 8;
            float z0 = sZ[r0], z1 = sZ[r1];
            #pragma unroll
            for (int nt = 0; nt < 8; nt++) {
                int c = ncol + nt * 8 + gc0;
                float w0 = sWz[c], w1 = sWz[c + 1], q0 = sBi[c], q1 = sBi[c + 1];
                float v00 = fmaxf(acc[mt][nt][0] + z0 * w0 + q0, 0.f);
                float v01 = fmaxf(acc[mt][nt][1] + z0 * w1 + q1, 0.f);
                float v10 = fmaxf(acc[mt][nt][2] + z1 * w0 + q0, 0.f);
                float v11 = fmaxf(acc[mt][nt][3] + z1 * w1 + q1, 0.f);
                *(__half2*)(sHA + r0 * LDA + c) = __floats2half2_rn(v00, v01);
                *(__half2*)(sHA + r1 * LDA + c) = __floats2half2_rn(v10, v11);
            }
        }
        __syncthreads();

        // prefetch next WiM into sWiM (dead after GEMM0), overlaps GEMM1/2
        if (i + 1 < 128) {
            const uint4* src = (const uint4*)(g_WiM + (size_t)(i + 1) * 16384);
            #pragma unroll
            for (int q = 0; q < 8; q++) {
                int v = q * 256 + tid, j = v >> 4, k = (v & 15) * 8;
                cpa16(sWiMA + (j * LDA + k) * 2, src + v);
            }
            asm volatile("cp.async.commit_group;\n");
        }

        // ---- GEMM1: h2 = relu(h1 @ W1^T + b1) ----
        gemm128(sHAA, sW1A, lane, mrow, ncol, acc);
        #pragma unroll
        for (int mt = 0; mt < 2; mt++) {
            int r0 = mrow + mt * 16 + gr0, r1 = r0 + 8;
            #pragma unroll
            for (int nt = 0; nt < 8; nt++) {
                int c = ncol + nt * 8 + gc0;
                float q0 = sB1[c], q1 = sB1[c + 1];
                float v00 = fmaxf(acc[mt][nt][0] + q0, 0.f);
                float v01 = fmaxf(acc[mt][nt][1] + q1, 0.f);
                float v10 = fmaxf(acc[mt][nt][2] + q0, 0.f);
                float v11 = fmaxf(acc[mt][nt][3] + q1, 0.f);
                *(__half2*)(sHB + r0 * LDA + c) = __floats2half2_rn(v00, v01);
                *(__half2*)(sHB + r1 * LDA + c) = __floats2half2_rn(v10, v11);
            }
        }
        __syncthreads();

        // ---- GEMM2 + fused fc_f (fp32 epilogue): o = relu(h2@W2^T+b2) @ Wf_i ----
        gemm128(sHBA, sW2A, lane, mrow, ncol, acc);
        {
            float p[2][2] = {{0.f, 0.f}, {0.f, 0.f}};
            #pragma unroll
            for (int mt = 0; mt < 2; mt++) {
                #pragma unroll
                for (int nt = 0; nt < 8; nt++) {
                    int c = ncol + nt * 8 + gc0;
                    float wf0 = sWf[c], wf1 = sWf[c + 1], q0 = sB2[c], q1 = sB2[c + 1];
                    p[mt][0] += fmaxf(acc[mt][nt][0] + q0, 0.f) * wf0
                              + fmaxf(acc[mt][nt][1] + q1, 0.f) * wf1;
                    p[mt][1] += fmaxf(acc[mt][nt][2] + q0, 0.f) * wf0
                              + fmaxf(acc[mt][nt][3] + q1, 0.f) * wf1;
                }
            }
            #pragma unroll
            for (int mt = 0; mt < 2; mt++)
                #pragma unroll
                for (int h = 0; h < 2; h++) {
                    float v = p[mt][h];
                    v += __shfl_xor_sync(0xffffffffu, v, 1);
                    v += __shfl_xor_sync(0xffffffffu, v, 2);
                    if ((lane & 3) == 0)
                        sO2[wn * 128 + mrow + mt * 16 + h * 8 + gr0] = v;  // deterministic, no atomics
                }
        }
        __syncthreads();

        // finalize: out[:, i] = o
        if (tid < 128) {
            float o = sO2[tid] + sO2[128 + tid] + bf[i];
            out[(b0 + tid) * 128 + i] = o;               // exact fp32 result to gmem
            sOut[tid * LDA + i] = __float2half(o);       // fp16 copy feeds later steps
        }
        asm volatile("cp.async.wait_group 0;\n");
        __syncthreads();
    }
}

// ---------------- host ----------------
extern "C" void kernel_launch(void* const* d_in, const int* in_sizes, int n_in,
                              void* d_out, int out_size) {
    const float* x  = (const float*)d_in[0];
    const float* z  = (const float*)d_in[1];
    const float* M  = (const float*)d_in[2];
    const float* Wi = (const float*)d_in[3];
    const float* bi = (const float*)d_in[4];
    const float* Wf = (const float*)d_in[5];
    const float* bf = (const float*)d_in[6];
    const float* W1 = (const float*)d_in[7];
    const float* b1 = (const float*)d_in[8];
    const float* W2 = (const float*)d_in[9];
    const float* b2 = (const float*)d_in[10];
    int Bn = in_sizes[0] / 128;

    cudaFuncSetAttribute(gen_main, cudaFuncAttributeMaxDynamicSharedMemorySize, SMEM_BYTES);

    prep_weights<<<130, 256>>>(Wi, M, W1, W2);
    transpose_z<<<dim3(Bn / 32, 4), dim3(32, 8)>>>(z, Bn);
    gen_main<<<Bn / TB, 256, SMEM_BYTES>>>(x, bi, Wf, bf, b1, b2, (float*)d_out, Bn);
}

// round 2
// speedup vs baseline: 1.0001x; 1.0001x over previous
#include <cuda_runtime.h>
#include <cuda_fp16.h>
#include <cstdint>

#define LDA 136          // padded row stride in halves (128 + 8) -> conflict-free ldmatrix
#define TB  128          // batch rows per CTA
#define SMEM_BYTES (6*128*LDA*2 + 1024*4)

// ---------------- scratch (device globals: no allocation allowed) ----------------
__device__ __half g_WiM[(size_t)128*128*128];   // [i][j][k] fp16, = Wi[i,j,k]*M[k,i]
__device__ float  g_wz [128*128];               // [i][j]  z-column weight (Wi[i,j,128])
__device__ __half g_W1h[128*128];
__device__ __half g_W2h[128*128];
__device__ float  g_zT [(size_t)128*131072];    // transposed z: [i][b]

// ---------------- prologue: weight prep ----------------
__global__ void prep_weights(const float* __restrict__ Wi, const float* __restrict__ M,
                             const float* __restrict__ W1, const float* __restrict__ W2) {
    int i = blockIdx.x;
    if (i < 128) {
        const float* Wii = Wi + (size_t)i * 16512;   // 128*129
        for (int v = threadIdx.x; v < 16384; v += blockDim.x) {
            int j = v >> 7, k = v & 127;
            float m = (k == i) ? 0.f : M[k * 128 + i];
            g_WiM[(size_t)i * 16384 + v] = __float2half(Wii[j * 129 + k] * m);
        }
        for (int j = threadIdx.x; j < 128; j += blockDim.x)
            g_wz[i * 128 + j] = Wii[j * 129 + 128];
    } else if (i == 128) {
        for (int v = threadIdx.x; v < 16384; v += blockDim.x) g_W1h[v] = __float2half(W1[v]);
    } else {
        for (int v = threadIdx.x; v < 16384; v += blockDim.x) g_W2h[v] = __float2half(W2[v]);
    }
}

// ---------------- prologue: z transpose ----------------
__global__ void transpose_z(const float* __restrict__ z, int Bn) {
    __shared__ float t[32][33];
    int b0 = blockIdx.x * 32, i0 = blockIdx.y * 32;
    #pragma unroll
    for (int r = threadIdx.y; r < 32; r += 8)
        t[r][threadIdx.x] = z[(size_t)(b0 + r) * 128 + i0 + threadIdx.x];
    __syncthreads();
    #pragma unroll
    for (int r = threadIdx.y; r < 32; r += 8)
        g_zT[(size_t)(i0 + r) * Bn + b0 + threadIdx.x] = t[threadIdx.x][r];
}

// ---------------- mma helpers ----------------
__device__ __forceinline__ void ldsm4(uint32_t addr, uint32_t* r) {
    asm volatile("ldmatrix.sync.aligned.m8n8.x4.shared.b16 {%0,%1,%2,%3},[%4];"
        : "=r"(r[0]), "=r"(r[1]), "=r"(r[2]), "=r"(r[3]) : "r"(addr));
}
__device__ __forceinline__ void mma16816(float* c, const uint32_t* a, const uint32_t* b) {
    asm volatile("mma.sync.aligned.m16n8k16.row.col.f32.f16.f16.f32 "
        "{%0,%1,%2,%3},{%4,%5,%6,%7},{%8,%9},{%0,%1,%2,%3};"
        : "+f"(c[0]), "+f"(c[1]), "+f"(c[2]), "+f"(c[3])
        : "r"(a[0]), "r"(a[1]), "r"(a[2]), "r"(a[3]), "r"(b[0]), "r"(b[1]));
}
__device__ __forceinline__ void cpa16(uint32_t s, const void* g) {
    asm volatile("cp.async.ca.shared.global [%0],[%1],16;\n" :: "r"(s), "l"(g));
}

// C[128,128] += A[128,128(k)] * B[128(n),128(k)]^T ; A,B fp16 in smem (padded LDA)
__device__ __forceinline__ void gemm128(uint32_t aBase, uint32_t bBase,
                                        int lane, int mrow, int ncol, float acc[2][8][4]) {
    #pragma unroll
    for (int mt = 0; mt < 2; mt++)
        #pragma unroll
        for (int nt = 0; nt < 8; nt++)
            #pragma unroll
            for (int c = 0; c < 4; c++) acc[mt][nt][c] = 0.f;

    uint32_t aOff = aBase + (uint32_t)(((mrow + (lane & 15)) * LDA + ((lane & 16) ? 8 : 0)) * 2);
    uint32_t bOff = bBase + (uint32_t)(((ncol + (lane & 7) + ((lane & 16) ? 8 : 0)) * LDA
                                       + ((lane & 8) ? 8 : 0)) * 2);
    #pragma unroll
    for (int ks = 0; ks < 8; ks++) {
        uint32_t kb = ks * 32;   // 16 halves
        uint32_t a0[4], a1[4], b[16];
        ldsm4(aOff + kb, a0);
        ldsm4(aOff + 16 * LDA * 2 + kb, a1);
        #pragma unroll
        for (int q = 0; q < 4; q++) ldsm4(bOff + q * 16 * LDA * 2 + kb, b + 4 * q);
        #pragma unroll
        for (int nt = 0; nt < 8; nt++) {
            const uint32_t* bb = b + (nt >> 1) * 4 + (nt & 1) * 2;
            mma16816(acc[0][nt], a0, bb);
            mma16816(acc[1][nt], a1, bb);
        }
    }
}

// ---------------- main persistent-tile scan kernel ----------------
__global__ __launch_bounds__(256, 1) void gen_main(
    const float* __restrict__ x,  const float* __restrict__ bi, const float* __restrict__ Wf,
    const float* __restrict__ bf, const float* __restrict__ b1, const float* __restrict__ b2,
    float* __restrict__ out, int Bn)
{
    extern __shared__ char smem_raw[];
    __half* sOut = (__half*)smem_raw;            // activations (fp16 "out" tile)
    __half* sHA  = sOut  + 128 * LDA;
    __half* sHB  = sHA   + 128 * LDA;
    __half* sWiM = sHB   + 128 * LDA;
    __half* sW1  = sWiM  + 128 * LDA;
    __half* sW2  = sW1   + 128 * LDA;
    float* sF  = (float*)(sW2 + 128 * LDA);
    float* sZ  = sF;        float* sWz = sF + 128;  float* sBi = sF + 256;
    float* sB1 = sF + 384;  float* sB2 = sF + 512;  float* sWf = sF + 640;
    float* sO2 = sF + 768;  // [2][128]

    int tid = threadIdx.x, lane = tid & 31, wid = tid >> 5;
    int wm = wid >> 1, wn = wid & 1;
    int mrow = wm * 32, ncol = wn * 64;
    int gr0 = lane >> 2, gc0 = 2 * (lane & 3);
    size_t b0 = (size_t)blockIdx.x * TB;

    uint32_t sOutA = (uint32_t)__cvta_generic_to_shared(sOut);
    uint32_t sHAA  = (uint32_t)__cvta_generic_to_shared(sHA);
    uint32_t sHBA  = (uint32_t)__cvta_generic_to_shared(sHB);
    uint32_t sWiMA = (uint32_t)__cvta_generic_to_shared(sWiM);
    uint32_t sW1A  = (uint32_t)__cvta_generic_to_shared(sW1);
    uint32_t sW2A  = (uint32_t)__cvta_generic_to_shared(sW2);

    // stage x -> sOut (fp16)
    const float4* xg = (const float4*)(x + b0 * 128);
    #pragma unroll
    for (int q = 0; q < 16; q++) {
        int v = q * 256 + tid;
        float4 f = xg[v];
        __half2* p = (__half2*)(sOut + (v >> 5) * LDA + (v & 31) * 4);
        p[0] = __floats2half2_rn(f.x, f.y);
        p[1] = __floats2half2_rn(f.z, f.w);
    }
    // stage W1, W2
    #pragma unroll
    for (int q = 0; q < 8; q++) {
        int v = q * 256 + tid, j = v >> 4, k = (v & 15) * 8;
        *(uint4*)(sW1 + j * LDA + k) = ((const uint4*)g_W1h)[v];
        *(uint4*)(sW2 + j * LDA + k) = ((const uint4*)g_W2h)[v];
    }
    if (tid < 128) { sB1[tid] = b1[tid]; sB2[tid] = b2[tid]; }
    // stage WiM_0 via cp.async
    {
        const uint4* src = (const uint4*)g_WiM;
        #pragma unroll
        for (int q = 0; q < 8; q++) {
            int v = q * 256 + tid, j = v >> 4, k = (v & 15) * 8;
            cpa16(sWiMA + (j * LDA + k) * 2, src + v);
        }
        asm volatile("cp.async.commit_group;\n");
        asm volatile("cp.async.wait_group 0;\n");
    }
    __syncthreads();

    float acc[2][8][4];
    for (int i = 0; i < 128; i++) {
        if (tid < 128) {
            sZ[tid]  = g_zT[(size_t)i * Bn + b0 + tid];
            sWz[tid] = g_wz[i * 128 + tid];
            sBi[tid] = bi[i * 128 + tid];
            sWf[tid] = Wf[i * 128 + tid];
        }
        __syncthreads();

        // ---- GEMM0: h1 = relu(out @ WiM^T + z*wz + bi) ----
        gemm128(sOutA, sWiMA, lane, mrow, ncol, acc);
        #pragma unroll
        for (int mt = 0; mt < 2; mt++) {
            int r0 = mrow + mt * 16 + gr0, r1 = r0 + 8;
            float z0 = sZ[r0], z1 = sZ[r1];
            #pragma unroll
            for (int nt = 0; nt < 8; nt++) {
                int c = ncol + nt * 8 + gc0;
                float w0 = sWz[c], w1 = sWz[c + 1], q0 = sBi[c], q1 = sBi[c + 1];
                float v00 = fmaxf(acc[mt][nt][0] + z0 * w0 + q0, 0.f);
                float v01 = fmaxf(acc[mt][nt][1] + z0 * w1 + q1, 0.f);
                float v10 = fmaxf(acc[mt][nt][2] + z1 * w0 + q0, 0.f);
                float v11 = fmaxf(acc[mt][nt][3] + z1 * w1 + q1, 0.f);
                *(__half2*)(sHA + r0 * LDA + c) = __floats2half2_rn(v00, v01);
                *(__half2*)(sHA + r1 * LDA + c) = __floats2half2_rn(v10, v11);
            }
        }
        __syncthreads();

        // prefetch next WiM into sWiM (dead after GEMM0), overlaps GEMM1/2
        if (i + 1 < 128) {
            const uint4* src = (const uint4*)(g_WiM + (size_t)(i + 1) * 16384);
            #pragma unroll
            for (int q = 0; q < 8; q++) {
                int v = q * 256 + tid, j = v >> 4, k = (v & 15) * 8;
                cpa16(sWiMA + (j * LDA + k) * 2, src + v);
            }
            asm volatile("cp.async.commit_group;\n");
        }

        // ---- GEMM1: h2 = relu(h1 @ W1^T + b1) ----
        gemm128(sHAA, sW1A, lane, mrow, ncol, acc);
        #pragma unroll
        for (int mt = 0; mt < 2; mt++) {
            int r0 = mrow + mt * 16 + gr0, r1 = r0 + 8;
            #pragma unroll
            for (int nt = 0; nt < 8; nt++) {
                int c = ncol + nt * 8 + gc0;
                float q0 = sB1[c], q1 = sB1[c + 1];
                float v00 = fmaxf(acc[mt][nt][0] + q0, 0.f);
                float v01 = fmaxf(acc[mt][nt][1] + q1, 0.f);
                float v10 = fmaxf(acc[mt][nt][2] + q0, 0.f);
                float v11 = fmaxf(acc[mt][nt][3] + q1, 0.f);
                *(__half2*)(sHB + r0 * LDA + c) = __floats2half2_rn(v00, v01);
                *(__half2*)(sHB + r1 * LDA + c) = __floats2half2_rn(v10, v11);
            }
        }
        __syncthreads();

        // ---- GEMM2 + fused fc_f (fp32 epilogue): o = relu(h2@W2^T+b2) @ Wf_i ----
        gemm128(sHBA, sW2A, lane, mrow, ncol, acc);
        {
            float p[2][2] = {{0.f, 0.f}, {0.f, 0.f}};
            #pragma unroll
            for (int mt = 0; mt < 2; mt++) {
                #pragma unroll
                for (int nt = 0; nt < 8; nt++) {
                    int c = ncol + nt * 8 + gc0;
                    float wf0 = sWf[c], wf1 = sWf[c + 1], q0 = sB2[c], q1 = sB2[c + 1];
                    p[mt][0] += fmaxf(acc[mt][nt][0] + q0, 0.f) * wf0
                              + fmaxf(acc[mt][nt][1] + q1, 0.f) * wf1;
                    p[mt][1] += fmaxf(acc[mt][nt][2] + q0, 0.f) * wf0
                              + fmaxf(acc[mt][nt][3] + q1, 0.f) * wf1;
                }
            }
            #pragma unroll
            for (int mt = 0; mt < 2; mt++)
                #pragma unroll
                for (int h = 0; h < 2; h++) {
                    float v = p[mt][h];
                    v += __shfl_xor_sync(0xffffffffu, v, 1);
                    v += __shfl_xor_sync(0xffffffffu, v, 2);
                    if ((lane & 3) == 0)
                        sO2[wn * 128 + mrow + mt * 16 + h * 8 + gr0] = v;  // deterministic, no atomics
                }
        }
        __syncthreads();

        // finalize: out[:, i] = o
        if (tid < 128) {
            float o = sO2[tid] + sO2[128 + tid] + bf[i];
            out[(b0 + tid) * 128 + i] = o;               // exact fp32 result to gmem
            sOut[tid * LDA + i] = __float2half(o);       // fp16 copy feeds later steps
        }
        asm volatile("cp.async.wait_group 0;\n");
        __syncthreads();
    }
}

// ---------------- host ----------------
extern "C" void kernel_launch(void* const* d_in, const int* in_sizes, int n_in,
                              void* d_out, int out_size) {
    const float* x  = (const float*)d_in[0];
    const float* z  = (const float*)d_in[1];
    const float* M  = (const float*)d_in[2];
    const float* Wi = (const float*)d_in[3];
    const float* bi = (const float*)d_in[4];
    const float* Wf = (const float*)d_in[5];
    const float* bf = (const float*)d_in[6];
    const float* W1 = (const float*)d_in[7];
    const float* b1 = (const float*)d_in[8];
    const float* W2 = (const float*)d_in[9];
    const float* b2 = (const float*)d_in[10];
    int Bn = in_sizes[0] / 128;

    cudaFuncSetAttribute(gen_main, cudaFuncAttributeMaxDynamicSharedMemorySize, SMEM_BYTES);

    prep_weights<<<130, 256>>>(Wi, M, W1, W2);
    transpose_z<<<dim3(Bn / 32, 4), dim3(32, 8)>>>(z, Bn);
    gen_main<<<Bn / TB, 256, SMEM_BYTES>>>(x, bi, Wf, bf, b1, b2, (float*)d_out, Bn);
}

// round 4
// speedup vs baseline: 1.0029x; 1.0028x over previous
#include <cuda_runtime.h>
#include <cuda_fp16.h>
#include <cstdint>

// ---- SMEM layout (bytes): 7 x 32KB unpadded swizzled fp16 tiles + small ----
#define OFF_OUTA 0
#define OFF_OUTB 32768
#define OFF_HA   65536
#define OFF_HB   98304
#define OFF_WIM  131072
#define OFF_W1   163840
#define OFF_W2   196608
#define OFF_C0   229376   // float2 (wz,bi)[128] = 1KB ; ALIASED as sO2 float[256]
#define OFF_WF   230400   // float[128]
#define OFF_B12  230912   // float2 (b1,b2)[128] = 1KB
#define SMEM_TOTAL 231936

// ---- device scratch ----
__device__ __half g_WiM[(size_t)128 * 16384];  // per-i swizzled 128x128 fp16 image
__device__ float  g_wz[128 * 128];
__device__ __half g_W1h[16384];                // swizzled image
__device__ __half g_W2h[16384];
__device__ float  g_zT[(size_t)128 * 131072];  // [i][b]

// XOR-swizzled byte offset in a 128x128 fp16 tile (row = 256B)
__host__ __device__ __forceinline__ uint32_t tile_off(int r, int c) {
    return (uint32_t)(r * 256 + ((c * 2) ^ ((r & 7) << 4)));
}

// ---- prologue kernels ----
__global__ void prep_weights(const float* __restrict__ Wi, const float* __restrict__ M,
                             const float* __restrict__ W1, const float* __restrict__ W2) {
    int i = blockIdx.x;
    if (i < 128) {
        const float* Wii = Wi + (size_t)i * 16512;   // 128*129
        for (int v = threadIdx.x; v < 16384; v += blockDim.x) {
            int j = v >> 7, k = v & 127;
            float m = (k == i) ? 0.f : M[k * 128 + i];
            g_WiM[(size_t)i * 16384 + (tile_off(j, k) >> 1)] = __float2half(Wii[j * 129 + k] * m);
        }
        for (int j = threadIdx.x; j < 128; j += blockDim.x)
            g_wz[i * 128 + j] = Wii[j * 129 + 128];
    } else if (i == 128) {
        for (int v = threadIdx.x; v < 16384; v += blockDim.x)
            g_W1h[tile_off(v >> 7, v & 127) >> 1] = __float2half(W1[v]);
    } else {
        for (int v = threadIdx.x; v < 16384; v += blockDim.x)
            g_W2h[tile_off(v >> 7, v & 127) >> 1] = __float2half(W2[v]);
    }
}

__global__ void transpose_z(const float* __restrict__ z, int Bn) {
    __shared__ float t[32][33];
    int b0 = blockIdx.x * 32, i0 = blockIdx.y * 32;
    #pragma unroll
    for (int r = threadIdx.y; r < 32; r += 8)
        t[r][threadIdx.x] = z[(size_t)(b0 + r) * 128 + i0 + threadIdx.x];
    __syncthreads();
    #pragma unroll
    for (int r = threadIdx.y; r < 32; r += 8)
        g_zT[(size_t)(i0 + r) * Bn + b0 + threadIdx.x] = t[threadIdx.x][r];
}

// ---- mma helpers ----
__device__ __forceinline__ void ldsm4(uint32_t addr, uint32_t* r) {
    asm volatile("ldmatrix.sync.aligned.m8n8.x4.shared.b16 {%0,%1,%2,%3},[%4];"
        : "=r"(r[0]), "=r"(r[1]), "=r"(r[2]), "=r"(r[3]) : "r"(addr));
}
__device__ __forceinline__ void mma16816(float* c, const uint32_t* a, const uint32_t* b) {
    asm volatile("mma.sync.aligned.m16n8k16.row.col.f32.f16.f16.f32 "
        "{%0,%1,%2,%3},{%4,%5,%6,%7},{%8,%9},{%0,%1,%2,%3};"
        : "+f"(c[0]), "+f"(c[1]), "+f"(c[2]), "+f"(c[3])
        : "r"(a[0]), "r"(a[1]), "r"(a[2]), "r"(a[3]), "r"(b[0]), "r"(b[1]));
}
__device__ __forceinline__ void cpa16(uint32_t s, const void* g) {
    asm volatile("cp.async.cg.shared.global [%0],[%1],16;" :: "r"(s), "l"(g));
}

// dual-tile GEMM: C{a,b}[128,128] = A{a,b}[128,k] * B[n,k]^T, B loaded ONCE per kstep
__device__ __forceinline__ void gemm2x(uint32_t aBaseA, uint32_t aBaseB, uint32_t bBase,
                                       int lane, int mrow, int ncol,
                                       float accA[2][8][4], float accB[2][8][4]) {
    #pragma unroll
    for (int mt = 0; mt < 2; mt++)
        #pragma unroll
        for (int nt = 0; nt < 8; nt++)
            #pragma unroll
            for (int c = 0; c < 4; c++) { accA[mt][nt][c] = 0.f; accB[mt][nt][c] = 0.f; }

    const int rA = mrow + (lane & 15);
    const uint32_t rowA0 = aBaseA + (uint32_t)(rA * 256);
    const uint32_t rowB0 = aBaseB + (uint32_t)(rA * 256);
    const uint32_t xorA = (uint32_t)((rA & 7) << 4);
    const uint32_t cA = (lane & 16) ? 16u : 0u;
    const int rB = ncol + (lane & 7) + ((lane & 16) ? 8 : 0);
    const uint32_t rowW = bBase + (uint32_t)(rB * 256);
    const uint32_t xorB = (uint32_t)((lane & 7) << 4);
    const uint32_t cB = (lane & 8) ? 16u : 0u;

    #pragma unroll
    for (int ks = 0; ks < 8; ks++) {
        uint32_t offA = ((uint32_t)(ks * 32) + cA) ^ xorA;
        uint32_t offB = ((uint32_t)(ks * 32) + cB) ^ xorB;
        uint32_t a0[4], a1[4], c0[4], c1[4], b[16];
        ldsm4(rowA0 + offA, a0);
        ldsm4(rowA0 + 4096 + offA, a1);
        ldsm4(rowB0 + offA, c0);
        ldsm4(rowB0 + 4096 + offA, c1);
        #pragma unroll
        for (int q = 0; q < 4; q++) ldsm4(rowW + (uint32_t)(q * 4096) + offB, b + 4 * q);
        #pragma unroll
        for (int nt = 0; nt < 8; nt++) {
            const uint32_t* bb = b + (nt >> 1) * 4 + (nt & 1) * 2;
            mma16816(accA[0][nt], a0, bb);
            mma16816(accA[1][nt], a1, bb);
            mma16816(accB[0][nt], c0, bb);
            mma16816(accB[1][nt], c1, bb);
        }
    }
}

// ---- main kernel: 1 CTA = 2 batch tiles of 128, interleaved legacy-HMMA ----
__global__ __launch_bounds__(256, 1)
void gen_main(const float* __restrict__ x,  const float* __restrict__ bi,
              const float* __restrict__ Wf, const float* __restrict__ bf,
              const float* __restrict__ b1, const float* __restrict__ b2,
              float* __restrict__ out, int Bn)
{
    extern __shared__ char sm[];
    const int tid = threadIdx.x, lane = tid & 31, wid = tid >> 5;
    const int wm = wid >> 1, wn = wid & 1;
    const int mrow = wm * 32, ncol = wn * 64;
    const int gr0 = lane >> 2, gc0 = 2 * (lane & 3);
    const size_t b0 = (size_t)blockIdx.x * 256;

    const uint32_t smBase = (uint32_t)__cvta_generic_to_shared(sm);
    const uint32_t aOutA = smBase + OFF_OUTA, aOutB = smBase + OFF_OUTB;
    const uint32_t aHA = smBase + OFF_HA, aHB = smBase + OFF_HB;
    const uint32_t aWiM = smBase + OFF_WIM, aW1 = smBase + OFF_W1, aW2 = smBase + OFF_W2;
    float2* sC0  = (float2*)(sm + OFF_C0);
    float*  sO2  = (float*)(sm + OFF_C0);      // alias; disjoint lifetime within step
    float*  sWf  = (float*)(sm + OFF_WF);
    float2* sB12 = (float2*)(sm + OFF_B12);

    // ---- stage x into both tiles (fp16, swizzled) ----
    const float4* xg = (const float4*)(x + b0 * 128);
    #pragma unroll
    for (int q = 0; q < 32; q++) {
        int v = (q << 8) + tid;                 // 0..8191 float4
        float4 f = xg[v];
        int rv = v >> 5, c4 = (v & 31) << 2;    // row 0..255, half col
        uint32_t off = tile_off(rv & 127, c4);
        char* base = sm + ((rv >> 7) ? OFF_OUTB : OFF_OUTA);
        *(__half2*)(base + off)     = __floats2half2_rn(f.x, f.y);
        *(__half2*)(base + off + 4) = __floats2half2_rn(f.z, f.w);
    }
    // ---- stage W1/W2 (pre-swizzled) + WiM(0) ----
    #pragma unroll
    for (int q = 0; q < 8; q++) {
        int v = (q << 8) + tid;
        ((uint4*)(sm + OFF_W1))[v] = ((const uint4*)g_W1h)[v];
        ((uint4*)(sm + OFF_W2))[v] = ((const uint4*)g_W2h)[v];
        cpa16(aWiM + (uint32_t)(v << 4), ((const uint4*)g_WiM) + v);
    }
    asm volatile("cp.async.commit_group;");
    if (tid < 128) sB12[tid] = make_float2(b1[tid], b2[tid]);
    asm volatile("cp.async.wait_group 0;");
    __syncthreads();

    float accA[2][8][4], accB[2][8][4];

    for (int i = 0; i < 128; i++) {
        // per-step coefficient staging
        if (tid < 128) {
            sC0[tid] = make_float2(g_wz[(i << 7) + tid], bi[(i << 7) + tid]);
            sWf[tid] = Wf[(i << 7) + tid];
        }
        const float bfi = bf[i];
        const float* zg = g_zT + (size_t)i * Bn + b0;
        __syncthreads();

        // ---- G0 pair: h1_pre = out @ WiM^T ----
        gemm2x(aOutA, aOutB, aWiM, lane, mrow, ncol, accA, accB);
        __syncthreads();                         // all WiM reads done
        // prefetch WiM(i+1) (overlaps rest of step)
        if (i < 127) {
            const uint4* src = (const uint4*)(g_WiM + (size_t)(i + 1) * 16384);
            #pragma unroll
            for (int q = 0; q < 8; q++) {
                int v = (q << 8) + tid;
                cpa16(aWiM + (uint32_t)(v << 4), src + v);
            }
            asm volatile("cp.async.commit_group;");
        }
        // ---- E0 pair: h1 = relu(pre + z*wz + bi) -> sHA/sHB ----
        #pragma unroll
        for (int t = 0; t < 2; t++) {
            float (*acc)[8][4] = t ? accB : accA;
            const uint32_t hB = t ? aHB : aHA;
            const float* zt = zg + (t << 7);
            #pragma unroll
            for (int mt = 0; mt < 2; mt++) {
                int r0 = mrow + mt * 16 + gr0, r1 = r0 + 8;
                float z0 = zt[r0], z1 = zt[r1];
                uint32_t row0 = hB + (uint32_t)(r0 * 256), row1 = hB + (uint32_t)(r1 * 256);
                uint32_t xr = (uint32_t)((r0 & 7) << 4);
                #pragma unroll
                for (int nt = 0; nt < 8; nt++) {
                    int c = ncol + nt * 8 + gc0;
                    float2 a0 = sC0[c], a1 = sC0[c + 1];
                    float v00 = fmaxf(fmaf(z0, a0.x, acc[mt][nt][0]) + a0.y, 0.f);
                    float v01 = fmaxf(fmaf(z0, a1.x, acc[mt][nt][1]) + a1.y, 0.f);
                    float v10 = fmaxf(fmaf(z1, a0.x, acc[mt][nt][2]) + a0.y, 0.f);
                    float v11 = fmaxf(fmaf(z1, a1.x, acc[mt][nt][3]) + a1.y, 0.f);
                    uint32_t cb = ((uint32_t)(2 * c)) ^ xr;
                    *(__half2*)(sm + (row0 + cb - smBase)) = __floats2half2_rn(v00, v01);
                    *(__half2*)(sm + (row1 + cb - smBase)) = __floats2half2_rn(v10, v11);
                }
            }
        }
        __syncthreads();

        // ---- G1 pair: h2_pre = h1 @ W1^T ----
        gemm2x(aHA, aHB, aW1, lane, mrow, ncol, accA, accB);
        __syncthreads();                         // h1 reads done before overwrite
        // ---- E1 pair: h2 = relu(pre + b1) in place ----
        #pragma unroll
        for (int t = 0; t < 2; t++) {
            float (*acc)[8][4] = t ? accB : accA;
            const uint32_t hB = t ? aHB : aHA;
            #pragma unroll
            for (int mt = 0; mt < 2; mt++) {
                int r0 = mrow + mt * 16 + gr0, r1 = r0 + 8;
                uint32_t row0 = hB + (uint32_t)(r0 * 256), row1 = hB + (uint32_t)(r1 * 256);
                uint32_t xr = (uint32_t)((r0 & 7) << 4);
                #pragma unroll
                for (int nt = 0; nt < 8; nt++) {
                    int c = ncol + nt * 8 + gc0;
                    float q0 = sB12[c].x, q1 = sB12[c + 1].x;
                    float v00 = fmaxf(acc[mt][nt][0] + q0, 0.f);
                    float v01 = fmaxf(acc[mt][nt][1] + q1, 0.f);
                    float v10 = fmaxf(acc[mt][nt][2] + q0, 0.f);
                    float v11 = fmaxf(acc[mt][nt][3] + q1, 0.f);
                    uint32_t cb = ((uint32_t)(2 * c)) ^ xr;
                    *(__half2*)(sm + (row0 + cb - smBase)) = __floats2half2_rn(v00, v01);
                    *(__half2*)(sm + (row1 + cb - smBase)) = __floats2half2_rn(v10, v11);
                }
            }
        }
        __syncthreads();

        // ---- G2 pair: h3_pre = h2 @ W2^T ----
        gemm2x(aHA, aHB, aW2, lane, mrow, ncol, accA, accB);

        // ---- E2: o = relu(pre + b2) @ Wf + bf ; write col i ----
        #pragma unroll
        for (int t = 0; t < 2; t++) {
            float (*acc)[8][4] = t ? accB : accA;
            float p[2][2] = {{0.f, 0.f}, {0.f, 0.f}};
            #pragma unroll
            for (int mt = 0; mt < 2; mt++)
                #pragma unroll
                for (int nt = 0; nt < 8; nt++) {
                    int c = ncol + nt * 8 + gc0;
                    float wf0 = sWf[c], wf1 = sWf[c + 1];
                    float q0 = sB12[c].y, q1 = sB12[c + 1].y;
                    p[mt][0] = fmaf(fmaxf(acc[mt][nt][0] + q0, 0.f), wf0,
                               fmaf(fmaxf(acc[mt][nt][1] + q1, 0.f), wf1, p[mt][0]));
                    p[mt][1] = fmaf(fmaxf(acc[mt][nt][2] + q0, 0.f), wf0,
                               fmaf(fmaxf(acc[mt][nt][3] + q1, 0.f), wf1, p[mt][1]));
                }
            __syncthreads();                     // sO2 free (prev use done)
            #pragma unroll
            for (int mt = 0; mt < 2; mt++)
                #pragma unroll
                for (int h = 0; h < 2; h++) {
                    float v = p[mt][h];
                    v += __shfl_xor_sync(0xffffffffu, v, 1);
                    v += __shfl_xor_sync(0xffffffffu, v, 2);
                    if ((lane & 3) == 0)
                        sO2[wn * 128 + mrow + mt * 16 + h * 8 + gr0] = v;
                }
            __syncthreads();
            if (tid < 128) {
                float o = sO2[tid] + sO2[128 + tid] + bfi;
                out[(b0 + (size_t)(t << 7) + tid) * 128 + i] = o;
                char* base = sm + (t ? OFF_OUTB : OFF_OUTA);
                *(__half*)(base + tile_off(tid, i)) = __float2half(o);
            }
        }
        if (i < 127) asm volatile("cp.async.wait_group 0;");
        __syncthreads();
    }
}

// ---- host ----
extern "C" void kernel_launch(void* const* d_in, const int* in_sizes, int n_in,
                              void* d_out, int out_size) {
    const float* x  = (const float*)d_in[0];
    const float* z  = (const float*)d_in[1];
    const float* M  = (const float*)d_in[2];
    const float* Wi = (const float*)d_in[3];
    const float* bi = (const float*)d_in[4];
    const float* Wf = (const float*)d_in[5];
    const float* bf = (const float*)d_in[6];
    const float* W1 = (const float*)d_in[7];
    const float* b1 = (const float*)d_in[8];
    const float* W2 = (const float*)d_in[9];
    const float* b2 = (const float*)d_in[10];
    int Bn = in_sizes[0] / 128;

    cudaFuncSetAttribute(gen_main, cudaFuncAttributeMaxDynamicSharedMemorySize, SMEM_TOTAL);

    prep_weights<<<130, 256>>>(Wi, M, W1, W2);
    transpose_z<<<dim3(Bn / 32, 4), dim3(32, 8)>>>(z, Bn);
    gen_main<<<Bn / 256, 256, SMEM_TOTAL>>>(x, bi, Wf, bf, b1, b2, (float*)d_out, Bn);
}